// round 6
// baseline (speedup 1.0000x reference)
#include <cuda_runtime.h>
#include <math.h>

#define D 256
#define HALF_D 128
#define MAXN 4096
#define NB 128            // blocks in persistent prep kernel (< 148 SMs -> co-resident)

// ---- device scratch (module-load zero-initialized; no allocations) ----
__device__ float g_M [D*D];   // dense skew: M[r][c]=+s, M[c][r]=-s (non-edges stay 0 forever)
__device__ float g_M2[D*D];   // M^2
__device__ float g_M4[D*D];   // M^4
__device__ float g_Y [D*D];   // Y = (M+M^2)(I+M^2) = M+M^2+M^3+M^4
__device__ float g_G [D*D];   // G = 2 Y (I+M^4) = 2(M+..+M^8) ~= R - I
__device__ float2 g_cs[MAXN*HALF_D]; // (cos,sin) per (position, freq-pair)

// grid-barrier state (replay-safe: cnt self-resets, sense read fresh at kernel start)
__device__ int g_cnt;
__device__ int g_sense;

// packed-f32x2 helpers (Blackwell f32x2 pipe, PTX-only)
#define FMA2(d, a, b) asm("fma.rn.f32x2 %0, %1, %2, %0;" : "+l"(d) : "l"(a), "l"(b))
#define DUP2(d, f)    asm("mov.b64 %0, {%1, %1};" : "=l"(d) : "r"(__float_as_uint(f)))

__device__ __forceinline__ void gridbar(int& ls) {
    __syncthreads();
    if (threadIdx.x == 0) {
        ls ^= 1;
        __threadfence();
        int v = atomicAdd(&g_cnt, 1);
        if (v == NB - 1) {
            g_cnt = 0;                 // reset for next use; fenced before release
            __threadfence();
            atomicExch(&g_sense, ls);  // release
        } else {
            while (atomicAdd(&g_sense, 0) != ls) { }
        }
        __threadfence();               // acquire
    }
    __syncthreads();
}

// ---------------- persistent prep: table+scatter -> M2 -> {Y, M4} -> G ----------------
// 128 blocks x 512 threads. Matmul phases: p = tid>>8 (row in 2-row tile), j = tid&255.
__global__ void __launch_bounds__(512) k_prep(
        const int* __restrict__ rows, const int* __restrict__ cols,
        const float* __restrict__ s, int E,
        const int* __restrict__ pos, const float* __restrict__ freqs, int N) {
    __shared__ float sA[2][D];
    __shared__ float sB[2][D];
    int tid = threadIdx.x;
    int bx  = blockIdx.x;
    int p   = tid >> 8;
    int j   = tid & 255;
    int r0  = bx * 2;

    // local barrier sense: read once before anyone can possibly flip it
    int ls = atomicAdd(&g_sense, 0);

    // -------- phase A: cos/sin table + edge scatter --------
    {
        int gtid = bx * 512 + tid;
        int tableN = N * HALF_D;
        const float INV2PI = 0.15915494309189535f;
        const float C1 = 6.2831854820251465f;           // float(2*pi)
        const float C2 = -1.7484556000744263e-7f;       // 2*pi - (double)C1
        for (int idx = gtid; idx < tableN; idx += NB * 512) {
            int n = idx >> 7, jj = idx & (HALF_D - 1);
            float ang = (float)pos[n] * freqs[jj];      // fp32 rounding matches ref
            float qf  = rintf(ang * INV2PI);
            float r   = fmaf(-qf, C1, ang);
            r = fmaf(-qf, C2, r);
            g_cs[idx] = make_float2(__cosf(r), __sinf(r));
        }
        for (int e = gtid; e < E; e += NB * 512) {
            int rr = rows[e], cc = cols[e];
            float v = s[e];
            g_M[rr*D + cc] =  v;                        // idempotent each replay
            g_M[cc*D + rr] = -v;
        }
    }
    gridbar(ls);

    // -------- phase B: M2 = M * M --------
    sA[p][j] = g_M[(r0 + p)*D + j];
    __syncthreads();
    {
        float acc = 0.f;
        #pragma unroll 2
        for (int kb = 0; kb < D; kb += 16) {
            float b[16];
            #pragma unroll
            for (int u = 0; u < 16; u++) b[u] = g_M[(kb + u)*D + j];
            #pragma unroll
            for (int u = 0; u < 16; u++) acc = fmaf(sA[p][kb + u], b[u], acc);
        }
        g_M2[(r0 + p)*D + j] = acc;
    }
    gridbar(ls);

    // -------- phase C: Y = X + X*M2 (X = M+M2)  and  M4 = M2*M2 (shared B loads) --------
    sA[p][j] = g_M[(r0 + p)*D + j] + g_M2[(r0 + p)*D + j];   // X rows
    sB[p][j] = g_M2[(r0 + p)*D + j];                          // M2 rows
    __syncthreads();
    {
        float accY = 0.f, acc4 = 0.f;
        #pragma unroll 2
        for (int kb = 0; kb < D; kb += 16) {
            float b[16];
            #pragma unroll
            for (int u = 0; u < 16; u++) b[u] = g_M2[(kb + u)*D + j];
            #pragma unroll
            for (int u = 0; u < 16; u++) {
                accY = fmaf(sA[p][kb + u], b[u], accY);
                acc4 = fmaf(sB[p][kb + u], b[u], acc4);
            }
        }
        g_Y [(r0 + p)*D + j] = sA[p][j] + accY;
        g_M4[(r0 + p)*D + j] = acc4;
    }
    gridbar(ls);

    // -------- phase D: G = 2*(Y + Y*M4) --------
    sA[p][j] = g_Y[(r0 + p)*D + j];
    __syncthreads();
    {
        float acc = 0.f;
        #pragma unroll 2
        for (int kb = 0; kb < D; kb += 16) {
            float b[16];
            #pragma unroll
            for (int u = 0; u < 16; u++) b[u] = g_M4[(kb + u)*D + j];
            #pragma unroll
            for (int u = 0; u < 16; u++) acc = fmaf(sA[p][kb + u], b[u], acc);
        }
        g_G[(r0 + p)*D + j] = 2.f * (sA[p][j] + acc);
    }
}

// ---------------- main GEMM: out = H + H*G, RoPE fused into A-tile load ----------------
// Block: 256 threads, tile 16 rows x 256 cols. Accumulators packed over ROW PAIRS
// in f32x2; G scalar duplicated once per (k, col).
__global__ void __launch_bounds__(256) k_gemm(const float* __restrict__ q,
                                              const float* __restrict__ kk,
                                              float* __restrict__ out,
                                              int BN, int N) {
    __shared__ __align__(16) float2 As2[8][D];   // [rowpair p][k] = (row 2p, row 2p+1)
    int t = threadIdx.x;
    int row0 = blockIdx.x * 16;

    // Fill A-tile with RoPE applied on the fly.
    for (int idx = t; idx < 16 * HALF_D; idx += 256) {
        int r  = idx >> 7;          // row within tile
        int jp = idx & (HALF_D-1);  // rotation pair
        int row = row0 + r;
        const float* src; int n;
        if (row < BN) { src = q  + (size_t)row*D;      n = row % N; }
        else          { src = kk + (size_t)(row-BN)*D; n = (row-BN) % N; }
        float2 v  = *(const float2*)(src + 2*jp);
        float2 cs = g_cs[n*HALF_D + jp];
        float e = v.x*cs.x - v.y*cs.y;
        float o = v.x*cs.y + v.y*cs.x;
        float* As2f = (float*)As2;
        int base = ((r >> 1)*D + 2*jp)*2 + (r & 1);
        As2f[base]     = e;
        As2f[base + 2] = o;
    }
    __syncthreads();

    int cg = t & 127;          // column group (2 cols)
    int rg = t >> 7;           // row group (8 rows)
    int j0 = cg * 2;
    int p0 = rg * 4;

    unsigned long long acc[4][2];
    #pragma unroll
    for (int pp = 0; pp < 4; pp++) { acc[pp][0] = 0ull; acc[pp][1] = 0ull; }

    #pragma unroll 8
    for (int k = 0; k < D; k += 2) {
        float2 gk0 = *(const float2*)&g_G[(size_t)k*D + j0];
        float2 gk1 = *(const float2*)&g_G[(size_t)(k+1)*D + j0];
        unsigned long long g00, g01, g10, g11;
        DUP2(g00, gk0.x); DUP2(g01, gk0.y);
        DUP2(g10, gk1.x); DUP2(g11, gk1.y);
        ulonglong2 Ap[4];
        #pragma unroll
        for (int pp = 0; pp < 4; pp++)
            Ap[pp] = *(const ulonglong2*)&As2[p0 + pp][k];
        #pragma unroll
        for (int pp = 0; pp < 4; pp++) {
            FMA2(acc[pp][0], Ap[pp].x, g00);
            FMA2(acc[pp][1], Ap[pp].x, g01);
            FMA2(acc[pp][0], Ap[pp].y, g10);
            FMA2(acc[pp][1], Ap[pp].y, g11);
        }
    }

    // Epilogue: out = H + correction; regroup packed row-pairs into per-row STG.64.
    #pragma unroll
    for (int pp = 0; pp < 4; pp++) {
        int p  = p0 + pp;
        int re = row0 + 2*p;
        float2 h0 = As2[p][j0];
        float2 h1 = As2[p][j0 + 1];
        unsigned long long a0 = acc[pp][0], a1 = acc[pp][1];
        float2 oe, oo;
        oe.x = h0.x + __uint_as_float((unsigned)a0);
        oe.y = h1.x + __uint_as_float((unsigned)a1);
        oo.x = h0.y + __uint_as_float((unsigned)(a0 >> 32));
        oo.y = h1.y + __uint_as_float((unsigned)(a1 >> 32));
        *(float2*)&out[(size_t)re*D     + j0] = oe;
        *(float2*)&out[(size_t)(re+1)*D + j0] = oo;
    }
}

// ---------------- launcher: 2 launches total ----------------
extern "C" void kernel_launch(void* const* d_in, const int* in_sizes, int n_in,
                              void* d_out, int out_size) {
    const float* q     = (const float*)d_in[0];
    const float* k     = (const float*)d_in[1];
    const float* freqs = (const float*)d_in[2];
    const float* sp    = (const float*)d_in[3];
    const int*   pos   = (const int*)  d_in[4];
    const int*   rows  = (const int*)  d_in[5];
    const int*   cols  = (const int*)  d_in[6];
    float* out = (float*)d_out;

    int E    = in_sizes[3];
    int N    = in_sizes[4];
    int BN   = in_sizes[0] / D;   // rows of q (= B*N)
    int ROWS = 2 * BN;

    k_prep<<<NB, 512>>>(rows, cols, sp, E, pos, freqs, N);
    k_gemm<<<ROWS/16, 256>>>(q, k, out, BN, N);
}

// round 7
// speedup vs baseline: 1.5828x; 1.5828x over previous
#include <cuda_runtime.h>
#include <math.h>

#define D 256
#define HALF_D 128
#define MAXN 4096
#define TM 128
#define TN 128
#define TK 32
#define SA_STRIDE 66   // f32x2 per k-row (pad: keeps 16B row alignment, spreads banks)

// ---- device scratch (module-load zero-initialized; no allocations) ----
__device__ float g_M [D*D];   // dense skew
__device__ float g_M2[D*D];
__device__ float g_M4[D*D];
__device__ float g_Y [D*D];   // Y = (M+M^2)(I+M^2)
__device__ float g_G [D*D];   // G = I + 2Y(I+M^4)  (full Cayley R, identity folded in)
__device__ float2 g_cs[MAXN*HALF_D];

// packed-f32x2 helpers (Blackwell f32x2 pipe, PTX-only)
#define FMA2(d, a, b) asm("fma.rn.f32x2 %0, %1, %2, %0;" : "+l"(d) : "l"(a), "l"(b))
#define DUP2(d, f)    asm("mov.b64 %0, {%1, %1};" : "=l"(d) : "r"(__float_as_uint(f)))

// ---------------- fused front: edge scatter + cos/sin table (all fp32) ----------------
__global__ void k_front(const int* __restrict__ rows, const int* __restrict__ cols,
                        const float* __restrict__ s, int E,
                        const int* __restrict__ pos, const float* __restrict__ freqs, int N) {
    int idx = blockIdx.x * blockDim.x + threadIdx.x;
    int tableN = N * HALF_D;
    if (idx < tableN) {
        int n = idx >> 7, j = idx & (HALF_D - 1);
        float ang = (float)pos[n] * freqs[j];
        const float INV2PI = 0.15915494309189535f;
        const float C1 = 6.2831854820251465f;
        const float C2 = -1.7484556000744263e-7f;
        float qf = rintf(ang * INV2PI);
        float r = fmaf(-qf, C1, ang);
        r = fmaf(-qf, C2, r);
        g_cs[idx] = make_float2(__cosf(r), __sinf(r));
    } else {
        int e = idx - tableN;
        if (e < E) {
            int r = rows[e], c = cols[e];
            float v = s[e];
            g_M[r*D + c] =  v;
            g_M[c*D + r] = -v;
        }
    }
}

// ---------------- dense 256x256 matmul steps (round-5 best config) ----------------
// 512 threads: p = tid>>8 (row in 2-row tile), j = tid&255 (col). 16-wide load batches.
// step 0 (grid 128): M2 = M*M
// step 1 (grid 256): bx<128: Y = X + X*M2 (X=M+M2); bx>=128: M4 = M2*M2
// step 2 (grid 128): G = I + 2*(Y + Y*M4)
__global__ void k_dmm(int step) {
    __shared__ float As[2][D];
    int tid = threadIdx.x;
    int p = tid >> 8;
    int j = tid & 255;
    int bx = blockIdx.x;

    const float* Bm;
    float* outp;
    int r0;
    float selfw, scale;

    if (step == 0) {
        r0 = bx*2; Bm = g_M;  outp = g_M2; selfw = 0.f; scale = 1.f;
        As[p][j] = g_M[(r0 + p)*D + j];
    } else if (step == 1) {
        if (bx < 128) {
            r0 = bx*2; Bm = g_M2; outp = g_Y; selfw = 1.f; scale = 1.f;
            As[p][j] = g_M[(r0 + p)*D + j] + g_M2[(r0 + p)*D + j];
        } else {
            r0 = (bx-128)*2; Bm = g_M2; outp = g_M4; selfw = 0.f; scale = 1.f;
            As[p][j] = g_M2[(r0 + p)*D + j];
        }
    } else {
        r0 = bx*2; Bm = g_M4; outp = g_G; selfw = 1.f; scale = 2.f;
        As[p][j] = g_Y[(r0 + p)*D + j];
    }
    __syncthreads();

    float acc = 0.f;
    #pragma unroll 4
    for (int k = 0; k < D; k += 8) {
        float b[8];
        #pragma unroll
        for (int u = 0; u < 8; u++) b[u] = Bm[(k + u)*D + j];
        #pragma unroll
        for (int u = 0; u < 8; u++) acc = fmaf(As[p][k + u], b[u], acc);
    }

    float res = scale * (acc + selfw * As[p][j]);
    if (step == 2 && (r0 + p) == j) res += 1.f;   // fold identity: G = R
    outp[(r0 + p)*D + j] = res;
}

// ---------------- main GEMM: out = H_rope * G  (G includes identity) ----------------
// 128x128 block tile, 256 threads, 8x8 register tile per thread (4 row-pair f32x2 x 8 cols).
// A chunks (TKx128) staged to shared with RoPE fused; next chunk prefetched into regs.
__global__ void __launch_bounds__(256, 2) k_gemm(const float* __restrict__ q,
                                                 const float* __restrict__ kk,
                                                 float* __restrict__ out,
                                                 int BN, int N) {
    __shared__ __align__(16) float2 sA[TK][SA_STRIDE];  // [kc][rowpair]
    __shared__ __align__(16) float  sB[TK][TN];         // [kc][col]

    const int t  = threadIdx.x;
    const int tx = t & 15;
    const int ty = t >> 4;
    const int row0 = blockIdx.x * TM;
    const int col0 = blockIdx.y * TN;

    // staging roles (independent of compute roles)
    const int jp = tx;     // pair-within-chunk 0..15
    const int pb = ty;     // rowpair base 0..15 (covers 0..63 with stride 16)

    // whole block is entirely in q or entirely in k (row0, BN multiples of 128)
    const float* src; int rb;
    if (row0 < BN) { src = q; rb = row0; } else { src = kk; rb = row0 - BN; }
    const int nb = rb % N;   // no wrap within a 128-row block (N >= 128)

    // prefetch A chunk 0 (two rows per slot)
    float2 v[4][2];
    {
        const float* base = src + (size_t)rb*D + 2*jp;
        #pragma unroll
        for (int i = 0; i < 4; i++) {
            const float* rp = base + (size_t)(2*(pb + 16*i))*D;
            v[i][0] = *(const float2*)rp;
            v[i][1] = *(const float2*)(rp + D);
        }
    }

    unsigned long long acc[4][8];
    #pragma unroll
    for (int pp = 0; pp < 4; pp++)
        #pragma unroll
        for (int cc = 0; cc < 8; cc++) acc[pp][cc] = 0ull;

    for (int c = 0; c < D/TK; c++) {
        const int jpg = c*16 + jp;      // global rotation pair

        // ---- stage A with RoPE (from prefetched regs) ----
        #pragma unroll
        for (int i = 0; i < 4; i++) {
            int p  = pb + 16*i;
            int n0 = nb + 2*p;
            float2 cs0 = g_cs[n0*HALF_D + jpg];
            float2 cs1 = g_cs[(n0+1)*HALF_D + jpg];
            float2 a = v[i][0], b2 = v[i][1];
            float e0 = a.x*cs0.x  - a.y*cs0.y;
            float o0 = a.x*cs0.y  + a.y*cs0.x;
            float e1 = b2.x*cs1.x - b2.y*cs1.y;
            float o1 = b2.x*cs1.y + b2.y*cs1.x;
            sA[2*jp  ][p] = make_float2(e0, e1);
            sA[2*jp+1][p] = make_float2(o0, o1);
        }
        // ---- stage B (G slice, L2-hot) ----
        #pragma unroll
        for (int i = 0; i < 4; i++) {
            int lin = i*256 + t;
            int kc = lin >> 5, c4 = lin & 31;
            float4 bb = *(const float4*)&g_G[(size_t)(c*TK + kc)*D + col0 + c4*4];
            *(float4*)&sB[kc][c4*4] = bb;
        }
        __syncthreads();

        // ---- prefetch next A chunk (LDGs fly during compute) ----
        if (c < D/TK - 1) {
            const float* base = src + (size_t)rb*D + 2*((c+1)*16 + jp);
            #pragma unroll
            for (int i = 0; i < 4; i++) {
                const float* rp = base + (size_t)(2*(pb + 16*i))*D;
                v[i][0] = *(const float2*)rp;
                v[i][1] = *(const float2*)(rp + D);
            }
        }

        // ---- compute 32 k-steps ----
        #pragma unroll 8
        for (int kc = 0; kc < TK; kc++) {
            ulonglong2 A0 = *(const ulonglong2*)&sA[kc][ty*4];      // pairs ty*4, +1
            ulonglong2 A1 = *(const ulonglong2*)&sA[kc][ty*4 + 2];  // pairs +2, +3
            float4 b0 = *(const float4*)&sB[kc][tx*4];
            float4 b1 = *(const float4*)&sB[kc][tx*4 + 64];
            unsigned long long g0,g1,g2,g3,g4,g5,g6,g7;
            DUP2(g0, b0.x); DUP2(g1, b0.y); DUP2(g2, b0.z); DUP2(g3, b0.w);
            DUP2(g4, b1.x); DUP2(g5, b1.y); DUP2(g6, b1.z); DUP2(g7, b1.w);
            unsigned long long Ap[4] = {A0.x, A0.y, A1.x, A1.y};
            #pragma unroll
            for (int pp = 0; pp < 4; pp++) {
                FMA2(acc[pp][0], Ap[pp], g0);
                FMA2(acc[pp][1], Ap[pp], g1);
                FMA2(acc[pp][2], Ap[pp], g2);
                FMA2(acc[pp][3], Ap[pp], g3);
                FMA2(acc[pp][4], Ap[pp], g4);
                FMA2(acc[pp][5], Ap[pp], g5);
                FMA2(acc[pp][6], Ap[pp], g6);
                FMA2(acc[pp][7], Ap[pp], g7);
            }
        }
        __syncthreads();
    }

    // ---- epilogue: unpack row-pair f32x2 accumulators, STG.128 per row segment ----
    #pragma unroll
    for (int pp = 0; pp < 4; pp++) {
        int re = row0 + (ty*4 + pp)*2;
        float4 lo0, hi0, lo1, hi1;
        lo0.x = __uint_as_float((unsigned)acc[pp][0]); hi0.x = __uint_as_float((unsigned)(acc[pp][0] >> 32));
        lo0.y = __uint_as_float((unsigned)acc[pp][1]); hi0.y = __uint_as_float((unsigned)(acc[pp][1] >> 32));
        lo0.z = __uint_as_float((unsigned)acc[pp][2]); hi0.z = __uint_as_float((unsigned)(acc[pp][2] >> 32));
        lo0.w = __uint_as_float((unsigned)acc[pp][3]); hi0.w = __uint_as_float((unsigned)(acc[pp][3] >> 32));
        lo1.x = __uint_as_float((unsigned)acc[pp][4]); hi1.x = __uint_as_float((unsigned)(acc[pp][4] >> 32));
        lo1.y = __uint_as_float((unsigned)acc[pp][5]); hi1.y = __uint_as_float((unsigned)(acc[pp][5] >> 32));
        lo1.z = __uint_as_float((unsigned)acc[pp][6]); hi1.z = __uint_as_float((unsigned)(acc[pp][6] >> 32));
        lo1.w = __uint_as_float((unsigned)acc[pp][7]); hi1.w = __uint_as_float((unsigned)(acc[pp][7] >> 32));
        *(float4*)&out[(size_t)re*D     + col0 + tx*4]      = lo0;
        *(float4*)&out[(size_t)(re+1)*D + col0 + tx*4]      = hi0;
        *(float4*)&out[(size_t)re*D     + col0 + 64 + tx*4] = lo1;
        *(float4*)&out[(size_t)(re+1)*D + col0 + 64 + tx*4] = hi1;
    }
}

// ---------------- launcher: 5 launches total ----------------
extern "C" void kernel_launch(void* const* d_in, const int* in_sizes, int n_in,
                              void* d_out, int out_size) {
    const float* q     = (const float*)d_in[0];
    const float* k     = (const float*)d_in[1];
    const float* freqs = (const float*)d_in[2];
    const float* sp    = (const float*)d_in[3];
    const int*   pos   = (const int*)  d_in[4];
    const int*   rows  = (const int*)  d_in[5];
    const int*   cols  = (const int*)  d_in[6];
    float* out = (float*)d_out;

    int E    = in_sizes[3];
    int N    = in_sizes[4];
    int BN   = in_sizes[0] / D;   // rows of q (= B*N)
    int ROWS = 2 * BN;

    int frontWork = N*HALF_D + E;
    k_front<<<(frontWork + 255)/256, 256>>>(rows, cols, sp, E, pos, freqs, N);

    k_dmm<<<128, 512>>>(0);   // M2 = M*M
    k_dmm<<<256, 512>>>(1);   // Y = (M+M2)(I+M2)  and  M4 = M2*M2
    k_dmm<<<128, 512>>>(2);   // G = I + 2 Y (I+M4)

    dim3 grid(ROWS/TM, D/TN);
    k_gemm<<<grid, 256>>>(q, k, out, BN, N);
}

// round 8
// speedup vs baseline: 1.5834x; 1.0004x over previous
#include <cuda_runtime.h>
#include <math.h>

#define D 256
#define HALF_D 128
#define MAXN 4096
#define TM 128
#define TN 128
#define TK 32
#define SA_STRIDE 66   // f32x2 per k-row (pad: keeps 16B row alignment, spreads banks)
#define EDGE_MAX 4096

// ---- device scratch (module-load zero-initialized; no allocations) ----
__device__ float g_G [D*D];          // G = R = I + 2(M + M^2 + ... + M^8)
__device__ float2 g_cs[MAXN*HALF_D]; // (cos,sin) per (position, freq-pair)

// packed-f32x2 helpers (Blackwell f32x2 pipe, PTX-only)
#define FMA2(d, a, b) asm("fma.rn.f32x2 %0, %1, %2, %0;" : "+l"(d) : "l"(a), "l"(b))
#define DUP2(d, f)    asm("mov.b64 %0, {%1, %1};" : "=l"(d) : "r"(__float_as_uint(f)))

// ---------------- fused prep: G columns (sparse Horner) + cos/sin table ----------------
// Blocks [0, D): block bx computes G[:, bx] via 8 sparse mat-vec Horner steps:
//   s <- M(e_j + s), M applied edge-wise with shared-memory atomics.
// Blocks [D, ...): cos/sin table entries.
__global__ void __launch_bounds__(256) k_prep(
        const int* __restrict__ rows, const int* __restrict__ cols,
        const float* __restrict__ sp, int E,
        const int* __restrict__ pos, const float* __restrict__ freqs, int N) {
    int bx = blockIdx.x;
    int t  = threadIdx.x;

    if (bx >= D) {
        // ---- cos/sin table ----
        int idx = (bx - D) * 256 + t;
        int tableN = N * HALF_D;
        if (idx < tableN) {
            int n = idx >> 7, j = idx & (HALF_D - 1);
            float ang = (float)pos[n] * freqs[j];       // fp32 rounding matches ref
            const float INV2PI = 0.15915494309189535f;
            const float C1 = 6.2831854820251465f;       // float(2*pi)
            const float C2 = -1.7484556000744263e-7f;   // 2*pi - (double)C1
            float qf = rintf(ang * INV2PI);
            float r  = fmaf(-qf, C1, ang);
            r = fmaf(-qf, C2, r);
            g_cs[idx] = make_float2(__cosf(r), __sinf(r));
        }
        return;
    }

    // ---- G column j = bx ----
    __shared__ int   sh_rc[EDGE_MAX];
    __shared__ float sh_v [EDGE_MAX];
    __shared__ float u[D];
    __shared__ float y[D];

    for (int e = t; e < E; e += 256) {
        sh_rc[e] = (rows[e] << 16) | cols[e];
        sh_v [e] = sp[e];
    }

    const int j = bx;
    float s = 0.f;                       // thread t owns element t of the column
    #pragma unroll 1
    for (int it = 0; it < 8; it++) {
        u[t] = s + (t == j ? 1.f : 0.f); // u = e_j + s
        y[t] = 0.f;
        __syncthreads();                 // (also covers initial edge staging)
        for (int e = t; e < E; e += 256) {
            int rc = sh_rc[e];
            float v = sh_v[e];
            int r = rc >> 16, c = rc & 0xFFFF;
            atomicAdd(&y[r],  v * u[c]); // y = M u (skew: +v at [r,c], -v at [c,r])
            atomicAdd(&y[c], -v * u[r]);
        }
        __syncthreads();
        s = y[t];
    }
    g_G[t*D + j] = 2.f * s + (t == j ? 1.f : 0.f);   // G = I + 2*Sum M^i
}

// ---------------- main GEMM: out = H_rope * G  (G includes identity) ----------------
// 128x128 block tile, 256 threads, 8x8 register tile per thread (4 row-pair f32x2 x 8 cols).
// A chunks (TKx128) staged to shared with RoPE fused; next chunk prefetched into regs.
__global__ void __launch_bounds__(256, 2) k_gemm(const float* __restrict__ q,
                                                 const float* __restrict__ kk,
                                                 float* __restrict__ out,
                                                 int BN, int N) {
    __shared__ __align__(16) float2 sA[TK][SA_STRIDE];  // [kc][rowpair]
    __shared__ __align__(16) float  sB[TK][TN];         // [kc][col]

    const int t  = threadIdx.x;
    const int tx = t & 15;
    const int ty = t >> 4;
    const int row0 = blockIdx.x * TM;
    const int col0 = blockIdx.y * TN;

    // staging roles (independent of compute roles)
    const int jp = tx;     // pair-within-chunk 0..15
    const int pb = ty;     // rowpair base 0..15 (covers 0..63 with stride 16)

    // whole block is entirely in q or entirely in k (row0, BN multiples of 128)
    const float* src; int rb;
    if (row0 < BN) { src = q; rb = row0; } else { src = kk; rb = row0 - BN; }
    const int nb = rb % N;   // no wrap within a 128-row block (N >= 128)

    // prefetch A chunk 0 (two rows per slot)
    float2 v[4][2];
    {
        const float* base = src + (size_t)rb*D + 2*jp;
        #pragma unroll
        for (int i = 0; i < 4; i++) {
            const float* rp = base + (size_t)(2*(pb + 16*i))*D;
            v[i][0] = *(const float2*)rp;
            v[i][1] = *(const float2*)(rp + D);
        }
    }

    unsigned long long acc[4][8];
    #pragma unroll
    for (int pp = 0; pp < 4; pp++)
        #pragma unroll
        for (int cc = 0; cc < 8; cc++) acc[pp][cc] = 0ull;

    for (int c = 0; c < D/TK; c++) {
        const int jpg = c*16 + jp;      // global rotation pair

        // ---- stage A with RoPE (from prefetched regs) ----
        #pragma unroll
        for (int i = 0; i < 4; i++) {
            int p  = pb + 16*i;
            int n0 = nb + 2*p;
            float2 cs0 = g_cs[n0*HALF_D + jpg];
            float2 cs1 = g_cs[(n0+1)*HALF_D + jpg];
            float2 a = v[i][0], b2 = v[i][1];
            float e0 = a.x*cs0.x  - a.y*cs0.y;
            float o0 = a.x*cs0.y  + a.y*cs0.x;
            float e1 = b2.x*cs1.x - b2.y*cs1.y;
            float o1 = b2.x*cs1.y + b2.y*cs1.x;
            sA[2*jp  ][p] = make_float2(e0, e1);
            sA[2*jp+1][p] = make_float2(o0, o1);
        }
        // ---- stage B (G slice, L2-hot) ----
        #pragma unroll
        for (int i = 0; i < 4; i++) {
            int lin = i*256 + t;
            int kc = lin >> 5, c4 = lin & 31;
            float4 bb = *(const float4*)&g_G[(size_t)(c*TK + kc)*D + col0 + c4*4];
            *(float4*)&sB[kc][c4*4] = bb;
        }
        __syncthreads();

        // ---- prefetch next A chunk (LDGs fly during compute) ----
        if (c < D/TK - 1) {
            const float* base = src + (size_t)rb*D + 2*((c+1)*16 + jp);
            #pragma unroll
            for (int i = 0; i < 4; i++) {
                const float* rp = base + (size_t)(2*(pb + 16*i))*D;
                v[i][0] = *(const float2*)rp;
                v[i][1] = *(const float2*)(rp + D);
            }
        }

        // ---- compute 32 k-steps ----
        #pragma unroll 8
        for (int kc = 0; kc < TK; kc++) {
            ulonglong2 A0 = *(const ulonglong2*)&sA[kc][ty*4];      // pairs ty*4, +1
            ulonglong2 A1 = *(const ulonglong2*)&sA[kc][ty*4 + 2];  // pairs +2, +3
            float4 b0 = *(const float4*)&sB[kc][tx*4];
            float4 b1 = *(const float4*)&sB[kc][tx*4 + 64];
            unsigned long long g0,g1,g2,g3,g4,g5,g6,g7;
            DUP2(g0, b0.x); DUP2(g1, b0.y); DUP2(g2, b0.z); DUP2(g3, b0.w);
            DUP2(g4, b1.x); DUP2(g5, b1.y); DUP2(g6, b1.z); DUP2(g7, b1.w);
            unsigned long long Ap[4] = {A0.x, A0.y, A1.x, A1.y};
            #pragma unroll
            for (int pp = 0; pp < 4; pp++) {
                FMA2(acc[pp][0], Ap[pp], g0);
                FMA2(acc[pp][1], Ap[pp], g1);
                FMA2(acc[pp][2], Ap[pp], g2);
                FMA2(acc[pp][3], Ap[pp], g3);
                FMA2(acc[pp][4], Ap[pp], g4);
                FMA2(acc[pp][5], Ap[pp], g5);
                FMA2(acc[pp][6], Ap[pp], g6);
                FMA2(acc[pp][7], Ap[pp], g7);
            }
        }
        __syncthreads();
    }

    // ---- epilogue: unpack row-pair f32x2 accumulators, STG.128 per row segment ----
    #pragma unroll
    for (int pp = 0; pp < 4; pp++) {
        int re = row0 + (ty*4 + pp)*2;
        float4 lo0, hi0, lo1, hi1;
        lo0.x = __uint_as_float((unsigned)acc[pp][0]); hi0.x = __uint_as_float((unsigned)(acc[pp][0] >> 32));
        lo0.y = __uint_as_float((unsigned)acc[pp][1]); hi0.y = __uint_as_float((unsigned)(acc[pp][1] >> 32));
        lo0.z = __uint_as_float((unsigned)acc[pp][2]); hi0.z = __uint_as_float((unsigned)(acc[pp][2] >> 32));
        lo0.w = __uint_as_float((unsigned)acc[pp][3]); hi0.w = __uint_as_float((unsigned)(acc[pp][3] >> 32));
        lo1.x = __uint_as_float((unsigned)acc[pp][4]); hi1.x = __uint_as_float((unsigned)(acc[pp][4] >> 32));
        lo1.y = __uint_as_float((unsigned)acc[pp][5]); hi1.y = __uint_as_float((unsigned)(acc[pp][5] >> 32));
        lo1.z = __uint_as_float((unsigned)acc[pp][6]); hi1.z = __uint_as_float((unsigned)(acc[pp][6] >> 32));
        lo1.w = __uint_as_float((unsigned)acc[pp][7]); hi1.w = __uint_as_float((unsigned)(acc[pp][7] >> 32));
        *(float4*)&out[(size_t)re*D     + col0 + tx*4]      = lo0;
        *(float4*)&out[(size_t)(re+1)*D + col0 + tx*4]      = hi0;
        *(float4*)&out[(size_t)re*D     + col0 + 64 + tx*4] = lo1;
        *(float4*)&out[(size_t)(re+1)*D + col0 + 64 + tx*4] = hi1;
    }
}

// ---------------- launcher: 2 launches total ----------------
extern "C" void kernel_launch(void* const* d_in, const int* in_sizes, int n_in,
                              void* d_out, int out_size) {
    const float* q     = (const float*)d_in[0];
    const float* k     = (const float*)d_in[1];
    const float* freqs = (const float*)d_in[2];
    const float* sp    = (const float*)d_in[3];
    const int*   pos   = (const int*)  d_in[4];
    const int*   rows  = (const int*)  d_in[5];
    const int*   cols  = (const int*)  d_in[6];
    float* out = (float*)d_out;

    int E    = in_sizes[3];
    int N    = in_sizes[4];
    int BN   = in_sizes[0] / D;   // rows of q (= B*N)
    int ROWS = 2 * BN;

    int tableBlocks = (N*HALF_D + 255)/256;
    k_prep<<<D + tableBlocks, 256>>>(rows, cols, sp, E, pos, freqs, N);

    dim3 grid(ROWS/TM, D/TN);
    k_gemm<<<grid, 256>>>(q, k, out, BN, N);
}